// round 1
// baseline (speedup 1.0000x reference)
#include <cuda_runtime.h>
#include <math.h>

#define SEQ 4096
#define DIM 1280
#define NHEAD 16
#define HD 80
#define HIDDEN 5120

// ---------------- scratch (device globals; no allocation allowed) ----------
__device__ float g_ln[SEQ * DIM];
__device__ float g_qkv[SEQ * 3 * DIM];
__device__ float g_attn[SEQ * DIM];
__device__ float g_h1[SEQ * DIM];
__device__ float g_fc1[SEQ * HIDDEN];

// ---------------- layernorm ------------------------------------------------
__global__ void ln_kernel(const float* __restrict__ x,
                          const float* __restrict__ sc,
                          const float* __restrict__ bi,
                          float* __restrict__ y) {
    int row = blockIdx.x;
    int t = threadIdx.x;
    const float* xr = x + (size_t)row * DIM;
    float s = 0.f, s2 = 0.f;
    #pragma unroll
    for (int i = t; i < DIM; i += 256) {
        float v = xr[i];
        s += v; s2 += v * v;
    }
    // warp reduce
    #pragma unroll
    for (int o = 16; o; o >>= 1) {
        s  += __shfl_xor_sync(~0u, s,  o);
        s2 += __shfl_xor_sync(~0u, s2, o);
    }
    __shared__ float sh[16];
    int wid = t >> 5, lane = t & 31;
    if (lane == 0) { sh[wid] = s; sh[wid + 8] = s2; }
    __syncthreads();
    float S = 0.f, S2 = 0.f;
    #pragma unroll
    for (int w = 0; w < 8; w++) { S += sh[w]; S2 += sh[w + 8]; }
    float mu = S * (1.f / DIM);
    float var = S2 * (1.f / DIM) - mu * mu;
    float inv = rsqrtf(var + 1e-6f);
    float* yr = y + (size_t)row * DIM;
    #pragma unroll
    for (int i = t; i < DIM; i += 256)
        yr[i] = (xr[i] - mu) * inv * sc[i] + bi[i];
}

// ---------------- SGEMM: C = A(MxK) * B(KxN) + bias, epilogue variants -----
// EPI 0: + bias        EPI 1: + bias + res        EPI 2: quickgelu(acc+bias)
template <int EPI>
__global__ void __launch_bounds__(256)
sgemm_k(const float* __restrict__ A, const float* __restrict__ B,
        const float* __restrict__ bias, const float* __restrict__ res,
        float* __restrict__ C, int M, int N, int K) {
    __shared__ float As[8][128];
    __shared__ float Bs[8][128];
    int t = threadIdx.x;
    int m0 = blockIdx.y * 128, n0 = blockIdx.x * 128;
    int tx = t & 15, ty = t >> 4;

    float acc[8][8];
    #pragma unroll
    for (int i = 0; i < 8; i++)
        #pragma unroll
        for (int j = 0; j < 8; j++) acc[i][j] = 0.f;

    int arow = t >> 1;         // 0..127
    int acol = (t & 1) * 4;    // 0 or 4
    int brow = t >> 5;         // 0..7
    int bcol = (t & 31) * 4;   // 0..124
    const float* Aptr = A + (size_t)(m0 + arow) * K + acol;
    const float* Bptr = B + (size_t)brow * N + n0 + bcol;

    for (int k0 = 0; k0 < K; k0 += 8) {
        float4 av = *(const float4*)(Aptr + k0);
        float4 bv = *(const float4*)(Bptr + (size_t)k0 * N);
        As[acol + 0][arow] = av.x;
        As[acol + 1][arow] = av.y;
        As[acol + 2][arow] = av.z;
        As[acol + 3][arow] = av.w;
        *(float4*)&Bs[brow][bcol] = bv;
        __syncthreads();
        #pragma unroll
        for (int kk = 0; kk < 8; kk++) {
            float ra[8], rb[8];
            *(float4*)(ra)     = *(const float4*)&As[kk][ty * 8];
            *(float4*)(ra + 4) = *(const float4*)&As[kk][ty * 8 + 4];
            *(float4*)(rb)     = *(const float4*)&Bs[kk][tx * 8];
            *(float4*)(rb + 4) = *(const float4*)&Bs[kk][tx * 8 + 4];
            #pragma unroll
            for (int i = 0; i < 8; i++)
                #pragma unroll
                for (int j = 0; j < 8; j++)
                    acc[i][j] += ra[i] * rb[j];
        }
        __syncthreads();
    }

    #pragma unroll
    for (int i = 0; i < 8; i++) {
        int m = m0 + ty * 8 + i;
        #pragma unroll
        for (int j = 0; j < 8; j++) {
            int n = n0 + tx * 8 + j;
            float v = acc[i][j] + bias[n];
            if (EPI == 1) v += res[(size_t)m * N + n];
            if (EPI == 2) v = v / (1.f + __expf(-1.702f * v));
            C[(size_t)m * N + n] = v;
        }
    }
}

// ---------------- RoPE on q and k (in place on qkv buffer) -----------------
__global__ void rope_kernel(float* __restrict__ qkv,
                            const float* __restrict__ freqs) {
    int n = blockIdx.x;
    int t = threadIdx.x;
    __shared__ float fc[40], fs[40];
    if (t < 40) {
        float f = freqs[(size_t)n * 40 + t];
        fc[t] = cosf(f);
        fs[t] = sinf(f);
    }
    __syncthreads();
    // 2 (q,k) * 16 heads * 40 pair-positions = 1280 items
    for (int i = t; i < 1280; i += 256) {
        int j = i / 640;            // 0:q 1:k
        int rem = i - j * 640;
        int h = rem / 40;
        int d = rem - h * 40;       // 0..39
        float* base = qkv + (size_t)n * (3 * DIM) + j * DIM + h * HD;
        float x1 = base[d];
        float x2 = base[d + 40];
        int plo = d >> 1;
        int phi = 20 + (d >> 1);
        base[d]      = x1 * fc[plo] - x2 * fs[plo];
        base[d + 40] = x2 * fc[phi] + x1 * fs[phi];
    }
}

// ---------------- flash attention (block-diagonal via cu_seqlens) ----------
#define BQ 64
#define BK 64
#define QSTR 84   // padded row stride for Q/K/V tiles (conflict-avoiding)
#define SSTR 68   // padded row stride for score tile

__global__ void __launch_bounds__(256)
flash_kernel(const float* __restrict__ qkv, const int* __restrict__ cu,
             float* __restrict__ out) {
    extern __shared__ float sm[];
    float* Qs = sm;                 // 64*84
    float* Ks = Qs + BQ * QSTR;     // 64*84
    float* Vs = Ks + BK * QSTR;     // 64*84
    float* Ss = Vs + BK * QSTR;     // 64*68
    __shared__ int sstart[BQ], send[BQ], sbound[2];

    int q0 = blockIdx.x * BQ;
    int h = blockIdx.y;
    int t = threadIdx.x;

    // Q tile
    for (int i = t; i < BQ * HD; i += 256) {
        int r = i / HD, d = i - r * HD;
        Qs[r * QSTR + d] = qkv[(size_t)(q0 + r) * (3 * DIM) + h * HD + d];
    }
    if (t < BQ) {
        int row = q0 + t;
        int s = 0, e = SEQ;
        #pragma unroll
        for (int i = 0; i < 4; i++)
            if (row >= cu[i] && row < cu[i + 1]) { s = cu[i]; e = cu[i + 1]; }
        sstart[t] = s; send[t] = e;
    }
    __syncthreads();
    if (t == 0) {
        int mn = sstart[0], mx = send[0];
        for (int i = 1; i < BQ; i++) {
            mn = min(mn, sstart[i]);
            mx = max(mx, send[i]);
        }
        sbound[0] = mn; sbound[1] = mx;
    }
    __syncthreads();
    int kmin = sbound[0], kmax = sbound[1];

    int qi = t >> 2;       // 0..63 query row
    int dg = t & 3;        // dim group, 20 dims each
    int mystart = sstart[qi], myend = send[qi];

    float acc[20];
    #pragma unroll
    for (int j = 0; j < 20; j++) acc[j] = 0.f;
    float m = -1e30f, l = 0.f;
    const float scale = 0.1118033988749895f;  // 1/sqrt(80)

    for (int kb = kmin; kb < kmax; kb += BK) {
        for (int i = t; i < BK * HD; i += 256) {
            int r = i / HD, d = i - r * HD;
            size_t base = (size_t)(kb + r) * (3 * DIM) + h * HD + d;
            Ks[r * QSTR + d] = qkv[base + DIM];
            Vs[r * QSTR + d] = qkv[base + 2 * DIM];
        }
        __syncthreads();

        // scores: this thread computes S[qi][kk*4+dg], kk=0..15
        float svals[16];
        float tmax = -1e30f;
        const float4* q4 = (const float4*)(Qs + qi * QSTR);
        #pragma unroll 4
        for (int kk = 0; kk < 16; kk++) {
            int k = kk * 4 + dg;
            const float4* k4 = (const float4*)(Ks + k * QSTR);
            float s = 0.f;
            #pragma unroll
            for (int d4 = 0; d4 < 20; d4++) {
                float4 qa = q4[d4];
                float4 ka = k4[d4];
                s += qa.x * ka.x + qa.y * ka.y + qa.z * ka.z + qa.w * ka.w;
            }
            int kg = kb + k;
            s = (kg >= mystart && kg < myend) ? s * scale : -1e30f;
            svals[kk] = s;
            tmax = fmaxf(tmax, s);
        }
        tmax = fmaxf(tmax, __shfl_xor_sync(~0u, tmax, 1));
        tmax = fmaxf(tmax, __shfl_xor_sync(~0u, tmax, 2));
        // clamp floor prevents exp(0) on fully masked tiles (no divergence)
        float newm = fmaxf(fmaxf(m, tmax), -1e28f);

        float psum = 0.f;
        #pragma unroll
        for (int kk = 0; kk < 16; kk++) {
            float p = __expf(svals[kk] - newm);
            psum += p;
            Ss[qi * SSTR + kk * 4 + dg] = p;
        }
        psum += __shfl_xor_sync(~0u, psum, 1);
        psum += __shfl_xor_sync(~0u, psum, 2);
        __syncwarp();

        float corr = __expf(m - newm);
        #pragma unroll
        for (int j = 0; j < 20; j++) acc[j] *= corr;
        for (int k = 0; k < BK; k++) {
            float p = Ss[qi * SSTR + k];
            const float4* v4 = (const float4*)(Vs + k * QSTR + dg * 20);
            #pragma unroll
            for (int jj = 0; jj < 5; jj++) {
                float4 vv = v4[jj];
                acc[jj * 4 + 0] += p * vv.x;
                acc[jj * 4 + 1] += p * vv.y;
                acc[jj * 4 + 2] += p * vv.z;
                acc[jj * 4 + 3] += p * vv.w;
            }
        }
        l = l * corr + psum;
        m = newm;
        __syncthreads();
    }

    float invl = 1.f / l;
    float* orow = out + (size_t)(q0 + qi) * DIM + h * HD + dg * 20;
    #pragma unroll
    for (int j = 0; j < 20; j++) orow[j] = acc[j] * invl;
}

// ---------------- launch ---------------------------------------------------
extern "C" void kernel_launch(void* const* d_in, const int* in_sizes, int n_in,
                              void* d_out, int out_size) {
    const float* hidden = (const float*)d_in[0];
    const float* rot    = (const float*)d_in[1];
    const int*   cu     = (const int*)d_in[2];
    const float* w_qkv  = (const float*)d_in[3];
    const float* b_qkv  = (const float*)d_in[4];
    const float* w_proj = (const float*)d_in[5];
    const float* b_proj = (const float*)d_in[6];
    const float* w_fc1  = (const float*)d_in[7];
    const float* b_fc1  = (const float*)d_in[8];
    const float* w_fc2  = (const float*)d_in[9];
    const float* b_fc2  = (const float*)d_in[10];
    const float* ln1s   = (const float*)d_in[11];
    const float* ln1b   = (const float*)d_in[12];
    const float* ln2s   = (const float*)d_in[13];
    const float* ln2b   = (const float*)d_in[14];
    float* out = (float*)d_out;

    float *ln, *qkvb, *attn, *h1, *fc1;
    cudaGetSymbolAddress((void**)&ln, g_ln);
    cudaGetSymbolAddress((void**)&qkvb, g_qkv);
    cudaGetSymbolAddress((void**)&attn, g_attn);
    cudaGetSymbolAddress((void**)&h1, g_h1);
    cudaGetSymbolAddress((void**)&fc1, g_fc1);

    const int FLASH_SMEM = (3 * BQ * QSTR + BQ * SSTR) * sizeof(float);
    cudaFuncSetAttribute(flash_kernel,
                         cudaFuncAttributeMaxDynamicSharedMemorySize,
                         FLASH_SMEM);

    // 1. LN1
    ln_kernel<<<SEQ, 256>>>(hidden, ln1s, ln1b, ln);
    // 2. QKV GEMM (+bias)
    sgemm_k<0><<<dim3((3 * DIM) / 128, SEQ / 128), 256>>>(
        ln, w_qkv, b_qkv, nullptr, qkvb, SEQ, 3 * DIM, DIM);
    // 3. RoPE on q,k
    rope_kernel<<<SEQ, 256>>>(qkvb, rot);
    // 4. attention
    flash_kernel<<<dim3(SEQ / BQ, NHEAD), 256, FLASH_SMEM>>>(qkvb, cu, attn);
    // 5. proj GEMM + bias + residual(hidden) -> h1
    sgemm_k<1><<<dim3(DIM / 128, SEQ / 128), 256>>>(
        attn, w_proj, b_proj, hidden, h1, SEQ, DIM, DIM);
    // 6. LN2
    ln_kernel<<<SEQ, 256>>>(h1, ln2s, ln2b, ln);
    // 7. FC1 + bias + quickgelu
    sgemm_k<2><<<dim3(HIDDEN / 128, SEQ / 128), 256>>>(
        ln, w_fc1, b_fc1, nullptr, fc1, SEQ, HIDDEN, DIM);
    // 8. FC2 + bias + residual(h1) -> out
    sgemm_k<1><<<dim3(DIM / 128, SEQ / 128), 256>>>(
        fc1, w_fc2, b_fc2, h1, out, SEQ, DIM, HIDDEN);
}

// round 2
// speedup vs baseline: 1.5822x; 1.5822x over previous
#include <cuda_runtime.h>
#include <math.h>
#include <stdint.h>

#define SEQ 4096
#define DIM 1280
#define NHEAD 16
#define HD 80
#define HIDDEN 5120

// ---------------- scratch (device globals; no allocation allowed) ----------
__device__ float g_ln[SEQ * DIM];
__device__ float g_qkv[SEQ * 3 * DIM];
__device__ float g_attn[SEQ * DIM];
__device__ float g_h1[SEQ * DIM];
__device__ float g_fc1[SEQ * HIDDEN];

// ---------------- layernorm ------------------------------------------------
__global__ void ln_kernel(const float* __restrict__ x,
                          const float* __restrict__ sc,
                          const float* __restrict__ bi,
                          float* __restrict__ y) {
    int row = blockIdx.x;
    int t = threadIdx.x;
    const float* xr = x + (size_t)row * DIM;
    float s = 0.f, s2 = 0.f;
    #pragma unroll
    for (int i = t; i < DIM; i += 256) {
        float v = xr[i];
        s += v; s2 += v * v;
    }
    #pragma unroll
    for (int o = 16; o; o >>= 1) {
        s  += __shfl_xor_sync(~0u, s,  o);
        s2 += __shfl_xor_sync(~0u, s2, o);
    }
    __shared__ float sh[16];
    int wid = t >> 5, lane = t & 31;
    if (lane == 0) { sh[wid] = s; sh[wid + 8] = s2; }
    __syncthreads();
    float S = 0.f, S2 = 0.f;
    #pragma unroll
    for (int w = 0; w < 8; w++) { S += sh[w]; S2 += sh[w + 8]; }
    float mu = S * (1.f / DIM);
    float var = S2 * (1.f / DIM) - mu * mu;
    float inv = rsqrtf(var + 1e-6f);
    float* yr = y + (size_t)row * DIM;
    #pragma unroll
    for (int i = t; i < DIM; i += 256)
        yr[i] = (xr[i] - mu) * inv * sc[i] + bi[i];
}

// ---------------- TF32 tensor-core GEMM ------------------------------------
// C = A(MxK) * B(KxN) + bias; EPI 0: bias, 1: bias+res, 2: quickgelu(bias)
#define BM 128
#define BN 128
#define BKT 16
#define ASTR 20   // row stride (floats): 8 rows hit banks {0,20,8,28,16,4,24,12}*4 -> conflict-free ldmatrix
#define BSTR 20

__device__ __forceinline__ float to_tf32(float x) {
    float r;
    asm("cvt.rna.tf32.f32 %0, %1;" : "=f"(r) : "f"(x));
    return r;
}

__device__ __forceinline__ uint32_t smem_u32(const void* p) {
    return (uint32_t)__cvta_generic_to_shared(p);
}

__device__ __forceinline__ void ldsm_x4(uint32_t& r0, uint32_t& r1,
                                        uint32_t& r2, uint32_t& r3,
                                        uint32_t addr) {
    asm volatile("ldmatrix.sync.aligned.m8n8.x4.shared.b16 {%0,%1,%2,%3},[%4];"
                 : "=r"(r0), "=r"(r1), "=r"(r2), "=r"(r3) : "r"(addr));
}

__device__ __forceinline__ void ldsm_x2(uint32_t& r0, uint32_t& r1,
                                        uint32_t addr) {
    asm volatile("ldmatrix.sync.aligned.m8n8.x2.shared.b16 {%0,%1},[%2];"
                 : "=r"(r0), "=r"(r1) : "r"(addr));
}

__device__ __forceinline__ void mma_tf32(float c[4],
                                         uint32_t a0, uint32_t a1,
                                         uint32_t a2, uint32_t a3,
                                         uint32_t b0, uint32_t b1) {
    asm volatile(
        "mma.sync.aligned.m16n8k8.row.col.f32.tf32.tf32.f32 "
        "{%0,%1,%2,%3},{%4,%5,%6,%7},{%8,%9},{%0,%1,%2,%3};"
        : "+f"(c[0]), "+f"(c[1]), "+f"(c[2]), "+f"(c[3])
        : "r"(a0), "r"(a1), "r"(a2), "r"(a3), "r"(b0), "r"(b1));
}

template <int EPI>
__global__ void __launch_bounds__(256)
tgemm(const float* __restrict__ A, const float* __restrict__ B,
      const float* __restrict__ bias, const float* __restrict__ res,
      float* __restrict__ C, int M, int N, int K) {
    __shared__ float As[2][BM * ASTR];
    __shared__ float Bs[2][BN * BSTR];
    int t = threadIdx.x;
    int lane = t & 31, warp = t >> 5;
    int wr = warp >> 2, wc = warp & 3;        // 2x4 warp grid
    int m0 = blockIdx.y * BM, n0 = blockIdx.x * BN;

    float acc[4][4][4];
    #pragma unroll
    for (int i = 0; i < 4; i++)
        #pragma unroll
        for (int j = 0; j < 4; j++)
            #pragma unroll
            for (int e = 0; e < 4; e++) acc[i][j][e] = 0.f;

    const float* Ag = A + (size_t)m0 * K;
    const float* Bg = B + n0;

    float4 ar[2], br[2];

    // A tile: 128m x 16k = 512 float4. i -> m=i>>2, kgroup=i&3
    // B tile: 16k x 128n = 512 float4. i -> k=i>>5, ngroup=i&31
    auto loadG = [&](int k0) {
        #pragma unroll
        for (int r = 0; r < 2; r++) {
            int ia = t + r * 256;
            ar[r] = *(const float4*)(Ag + (size_t)(ia >> 2) * K + k0 + (ia & 3) * 4);
            br[r] = *(const float4*)(Bg + (size_t)(k0 + (ia >> 5)) * N + (ia & 31) * 4);
        }
    };
    auto storeS = [&](int buf) {
        #pragma unroll
        for (int r = 0; r < 2; r++) {
            int ia = t + r * 256;
            float* ap = &As[buf][(ia >> 2) * ASTR + (ia & 3) * 4];
            ap[0] = to_tf32(ar[r].x); ap[1] = to_tf32(ar[r].y);
            ap[2] = to_tf32(ar[r].z); ap[3] = to_tf32(ar[r].w);
            int k = ia >> 5, n = (ia & 31) * 4;
            Bs[buf][(n + 0) * BSTR + k] = to_tf32(br[r].x);
            Bs[buf][(n + 1) * BSTR + k] = to_tf32(br[r].y);
            Bs[buf][(n + 2) * BSTR + k] = to_tf32(br[r].z);
            Bs[buf][(n + 3) * BSTR + k] = to_tf32(br[r].w);
        }
    };

    loadG(0);
    storeS(0);
    __syncthreads();

    int nk = K / BKT;
    int sub = lane >> 3, srow = lane & 7;   // ldmatrix addressing

    for (int kt = 0; kt < nk; kt++) {
        int cur = kt & 1;
        if (kt + 1 < nk) loadG((kt + 1) * BKT);

        #pragma unroll
        for (int ks = 0; ks < 2; ks++) {
            int k0 = ks * 8;
            uint32_t af[4][4], bf[4][2];
            #pragma unroll
            for (int i = 0; i < 4; i++) {
                const float* base = &As[cur][(wr * 64 + i * 16 + (sub & 1) * 8 + srow) * ASTR
                                            + k0 + (sub >> 1) * 4];
                ldsm_x4(af[i][0], af[i][1], af[i][2], af[i][3], smem_u32(base));
            }
            #pragma unroll
            for (int j = 0; j < 4; j++) {
                const float* base = &Bs[cur][(wc * 32 + j * 8 + srow) * BSTR
                                            + k0 + (sub & 1) * 4];
                ldsm_x2(bf[j][0], bf[j][1], smem_u32(base));
            }
            #pragma unroll
            for (int i = 0; i < 4; i++)
                #pragma unroll
                for (int j = 0; j < 4; j++)
                    mma_tf32(acc[i][j], af[i][0], af[i][1], af[i][2], af[i][3],
                             bf[j][0], bf[j][1]);
        }

        if (kt + 1 < nk) storeS(cur ^ 1);
        __syncthreads();
    }

    // epilogue: thread holds c[e]: rows g,g+8 cols 2*tig,2*tig+1 per frag
    int g = lane >> 2, tig = lane & 3;
    #pragma unroll
    for (int i = 0; i < 4; i++) {
        int mrow = m0 + wr * 64 + i * 16 + g;
        #pragma unroll
        for (int j = 0; j < 4; j++) {
            int ncol = n0 + wc * 32 + j * 8 + tig * 2;
            #pragma unroll
            for (int e = 0; e < 4; e++) {
                int mm = mrow + (e >> 1) * 8;
                int nn = ncol + (e & 1);
                float v = acc[i][j][e] + bias[nn];
                if (EPI == 1) v += res[(size_t)mm * N + nn];
                if (EPI == 2) v = v / (1.f + __expf(-1.702f * v));
                C[(size_t)mm * N + nn] = v;
            }
        }
    }
}

// ---------------- RoPE on q and k (in place on qkv buffer) -----------------
__global__ void rope_kernel(float* __restrict__ qkv,
                            const float* __restrict__ freqs) {
    int n = blockIdx.x;
    int t = threadIdx.x;
    __shared__ float fc[40], fs[40];
    if (t < 40) {
        float f = freqs[(size_t)n * 40 + t];
        fc[t] = cosf(f);
        fs[t] = sinf(f);
    }
    __syncthreads();
    for (int i = t; i < 1280; i += 256) {
        int j = i / 640;
        int rem = i - j * 640;
        int h = rem / 40;
        int d = rem - h * 40;
        float* base = qkv + (size_t)n * (3 * DIM) + j * DIM + h * HD;
        float x1 = base[d];
        float x2 = base[d + 40];
        int plo = d >> 1;
        int phi = 20 + (d >> 1);
        base[d]      = x1 * fc[plo] - x2 * fs[plo];
        base[d + 40] = x2 * fc[phi] + x1 * fs[phi];
    }
}

// ---------------- flash attention (block-diagonal via cu_seqlens) ----------
#define BQ 64
#define BK 64
#define QSTR 84
#define SSTR 68

__global__ void __launch_bounds__(256)
flash_kernel(const float* __restrict__ qkv, const int* __restrict__ cu,
             float* __restrict__ out) {
    extern __shared__ float sm[];
    float* Qs = sm;
    float* Ks = Qs + BQ * QSTR;
    float* Vs = Ks + BK * QSTR;
    float* Ss = Vs + BK * QSTR;
    __shared__ int sstart[BQ], send[BQ], sbound[2];

    int q0 = blockIdx.x * BQ;
    int h = blockIdx.y;
    int t = threadIdx.x;

    for (int i = t; i < BQ * HD; i += 256) {
        int r = i / HD, d = i - r * HD;
        Qs[r * QSTR + d] = qkv[(size_t)(q0 + r) * (3 * DIM) + h * HD + d];
    }
    if (t < BQ) {
        int row = q0 + t;
        int s = 0, e = SEQ;
        #pragma unroll
        for (int i = 0; i < 4; i++)
            if (row >= cu[i] && row < cu[i + 1]) { s = cu[i]; e = cu[i + 1]; }
        sstart[t] = s; send[t] = e;
    }
    __syncthreads();
    if (t == 0) {
        int mn = sstart[0], mx = send[0];
        for (int i = 1; i < BQ; i++) {
            mn = min(mn, sstart[i]);
            mx = max(mx, send[i]);
        }
        sbound[0] = mn; sbound[1] = mx;
    }
    __syncthreads();
    int kmin = sbound[0], kmax = sbound[1];

    int qi = t >> 2;
    int dg = t & 3;
    int mystart = sstart[qi], myend = send[qi];

    float acc[20];
    #pragma unroll
    for (int j = 0; j < 20; j++) acc[j] = 0.f;
    float m = -1e30f, l = 0.f;
    const float scale = 0.1118033988749895f;

    for (int kb = kmin; kb < kmax; kb += BK) {
        for (int i = t; i < BK * HD; i += 256) {
            int r = i / HD, d = i - r * HD;
            size_t base = (size_t)(kb + r) * (3 * DIM) + h * HD + d;
            Ks[r * QSTR + d] = qkv[base + DIM];
            Vs[r * QSTR + d] = qkv[base + 2 * DIM];
        }
        __syncthreads();

        float svals[16];
        float tmax = -1e30f;
        const float4* q4 = (const float4*)(Qs + qi * QSTR);
        #pragma unroll 4
        for (int kk = 0; kk < 16; kk++) {
            int k = kk * 4 + dg;
            const float4* k4 = (const float4*)(Ks + k * QSTR);
            float s = 0.f;
            #pragma unroll
            for (int d4 = 0; d4 < 20; d4++) {
                float4 qa = q4[d4];
                float4 ka = k4[d4];
                s += qa.x * ka.x + qa.y * ka.y + qa.z * ka.z + qa.w * ka.w;
            }
            int kg = kb + k;
            s = (kg >= mystart && kg < myend) ? s * scale : -1e30f;
            svals[kk] = s;
            tmax = fmaxf(tmax, s);
        }
        tmax = fmaxf(tmax, __shfl_xor_sync(~0u, tmax, 1));
        tmax = fmaxf(tmax, __shfl_xor_sync(~0u, tmax, 2));
        float newm = fmaxf(fmaxf(m, tmax), -1e28f);

        float psum = 0.f;
        #pragma unroll
        for (int kk = 0; kk < 16; kk++) {
            float p = __expf(svals[kk] - newm);
            psum += p;
            Ss[qi * SSTR + kk * 4 + dg] = p;
        }
        psum += __shfl_xor_sync(~0u, psum, 1);
        psum += __shfl_xor_sync(~0u, psum, 2);
        __syncwarp();

        float corr = __expf(m - newm);
        #pragma unroll
        for (int j = 0; j < 20; j++) acc[j] *= corr;
        for (int k = 0; k < BK; k++) {
            float p = Ss[qi * SSTR + k];
            const float4* v4 = (const float4*)(Vs + k * QSTR + dg * 20);
            #pragma unroll
            for (int jj = 0; jj < 5; jj++) {
                float4 vv = v4[jj];
                acc[jj * 4 + 0] += p * vv.x;
                acc[jj * 4 + 1] += p * vv.y;
                acc[jj * 4 + 2] += p * vv.z;
                acc[jj * 4 + 3] += p * vv.w;
            }
        }
        l = l * corr + psum;
        m = newm;
        __syncthreads();
    }

    float invl = 1.f / l;
    float* orow = out + (size_t)(q0 + qi) * DIM + h * HD + dg * 20;
    #pragma unroll
    for (int j = 0; j < 20; j++) orow[j] = acc[j] * invl;
}

// ---------------- launch ---------------------------------------------------
extern "C" void kernel_launch(void* const* d_in, const int* in_sizes, int n_in,
                              void* d_out, int out_size) {
    const float* hidden = (const float*)d_in[0];
    const float* rot    = (const float*)d_in[1];
    const int*   cu     = (const int*)d_in[2];
    const float* w_qkv  = (const float*)d_in[3];
    const float* b_qkv  = (const float*)d_in[4];
    const float* w_proj = (const float*)d_in[5];
    const float* b_proj = (const float*)d_in[6];
    const float* w_fc1  = (const float*)d_in[7];
    const float* b_fc1  = (const float*)d_in[8];
    const float* w_fc2  = (const float*)d_in[9];
    const float* b_fc2  = (const float*)d_in[10];
    const float* ln1s   = (const float*)d_in[11];
    const float* ln1b   = (const float*)d_in[12];
    const float* ln2s   = (const float*)d_in[13];
    const float* ln2b   = (const float*)d_in[14];
    float* out = (float*)d_out;

    float *ln, *qkvb, *attn, *h1, *fc1;
    cudaGetSymbolAddress((void**)&ln, g_ln);
    cudaGetSymbolAddress((void**)&qkvb, g_qkv);
    cudaGetSymbolAddress((void**)&attn, g_attn);
    cudaGetSymbolAddress((void**)&h1, g_h1);
    cudaGetSymbolAddress((void**)&fc1, g_fc1);

    const int FLASH_SMEM = (3 * BQ * QSTR + BQ * SSTR) * sizeof(float);
    cudaFuncSetAttribute(flash_kernel,
                         cudaFuncAttributeMaxDynamicSharedMemorySize,
                         FLASH_SMEM);

    // 1. LN1
    ln_kernel<<<SEQ, 256>>>(hidden, ln1s, ln1b, ln);
    // 2. QKV GEMM (+bias)
    tgemm<0><<<dim3((3 * DIM) / BN, SEQ / BM), 256>>>(
        ln, w_qkv, b_qkv, nullptr, qkvb, SEQ, 3 * DIM, DIM);
    // 3. RoPE on q,k
    rope_kernel<<<SEQ, 256>>>(qkvb, rot);
    // 4. attention
    flash_kernel<<<dim3(SEQ / BQ, NHEAD), 256, FLASH_SMEM>>>(qkvb, cu, attn);
    // 5. proj GEMM + bias + residual(hidden) -> h1
    tgemm<1><<<dim3(DIM / BN, SEQ / BM), 256>>>(
        attn, w_proj, b_proj, hidden, h1, SEQ, DIM, DIM);
    // 6. LN2
    ln_kernel<<<SEQ, 256>>>(h1, ln2s, ln2b, ln);
    // 7. FC1 + bias + quickgelu
    tgemm<2><<<dim3(HIDDEN / BN, SEQ / BM), 256>>>(
        ln, w_fc1, b_fc1, nullptr, fc1, SEQ, HIDDEN, DIM);
    // 8. FC2 + bias + residual(h1) -> out
    tgemm<1><<<dim3(DIM / BN, SEQ / BM), 256>>>(
        fc1, w_fc2, b_fc2, h1, out, SEQ, DIM, HIDDEN);
}

// round 5
// speedup vs baseline: 2.2779x; 1.4397x over previous
#include <cuda_runtime.h>
#include <math.h>
#include <stdint.h>

#define SEQ 4096
#define DIM 1280
#define NHEAD 16
#define HD 80
#define HIDDEN 5120

// ---------------- scratch (device globals; no allocation allowed) ----------
__device__ float g_ln[SEQ * DIM];
__device__ float g_qkv[SEQ * 3 * DIM];
__device__ float g_attn[SEQ * DIM];
__device__ float g_h1[SEQ * DIM];
__device__ float g_fc1[SEQ * HIDDEN];

// ---------------- layernorm ------------------------------------------------
__global__ void ln_kernel(const float* __restrict__ x,
                          const float* __restrict__ sc,
                          const float* __restrict__ bi,
                          float* __restrict__ y) {
    int row = blockIdx.x;
    int t = threadIdx.x;
    const float* xr = x + (size_t)row * DIM;
    float s = 0.f, s2 = 0.f;
    #pragma unroll
    for (int i = t; i < DIM; i += 256) {
        float v = xr[i];
        s += v; s2 += v * v;
    }
    #pragma unroll
    for (int o = 16; o; o >>= 1) {
        s  += __shfl_xor_sync(~0u, s,  o);
        s2 += __shfl_xor_sync(~0u, s2, o);
    }
    __shared__ float sh[16];
    int wid = t >> 5, lane = t & 31;
    if (lane == 0) { sh[wid] = s; sh[wid + 8] = s2; }
    __syncthreads();
    float S = 0.f, S2 = 0.f;
    #pragma unroll
    for (int w = 0; w < 8; w++) { S += sh[w]; S2 += sh[w + 8]; }
    float mu = S * (1.f / DIM);
    float var = S2 * (1.f / DIM) - mu * mu;
    float inv = rsqrtf(var + 1e-6f);
    float* yr = y + (size_t)row * DIM;
    #pragma unroll
    for (int i = t; i < DIM; i += 256)
        yr[i] = (xr[i] - mu) * inv * sc[i] + bi[i];
}

// ---------------- TF32 tensor-core GEMM, 4-stage cp.async pipeline ---------
// C = A(MxK) * B(KxN) + bias; EPI 0: bias, 1: bias+res, 2: quickgelu(bias)
#define BM 128
#define BN 128
#define BKT 16
#define ASTR 20    // A row stride: rows hit banks {0,20,8,28,16,4,24,12}*4 -> ldmatrix conflict-free
#define BSN 136    // B row stride: 136 mod 32 = 8 -> LDS frag addrs 8k+g cover all banks
#define NSTAGE 4
#define A_ST (BM * ASTR)      // 2560 floats / stage
#define B_ST (BKT * BSN)      // 2176 floats / stage
#define GSMEM ((NSTAGE * (A_ST + B_ST)) * sizeof(float))  // 75776 B

__device__ __forceinline__ uint32_t smem_u32(const void* p) {
    return (uint32_t)__cvta_generic_to_shared(p);
}

__device__ __forceinline__ void cp16(uint32_t dst, const void* src) {
    asm volatile("cp.async.cg.shared.global [%0], [%1], 16;"
                 :: "r"(dst), "l"(src));
}
__device__ __forceinline__ void cp_commit() {
    asm volatile("cp.async.commit_group;");
}
template <int N>
__device__ __forceinline__ void cp_wait() {
    asm volatile("cp.async.wait_group %0;" :: "n"(N));
}

__device__ __forceinline__ void ldsm_x4(uint32_t& r0, uint32_t& r1,
                                        uint32_t& r2, uint32_t& r3,
                                        uint32_t addr) {
    asm volatile("ldmatrix.sync.aligned.m8n8.x4.shared.b16 {%0,%1,%2,%3},[%4];"
                 : "=r"(r0), "=r"(r1), "=r"(r2), "=r"(r3) : "r"(addr));
}

__device__ __forceinline__ void mma_tf32(float c[4],
                                         uint32_t a0, uint32_t a1,
                                         uint32_t a2, uint32_t a3,
                                         uint32_t b0, uint32_t b1) {
    asm volatile(
        "mma.sync.aligned.m16n8k8.row.col.f32.tf32.tf32.f32 "
        "{%0,%1,%2,%3},{%4,%5,%6,%7},{%8,%9},{%0,%1,%2,%3};"
        : "+f"(c[0]), "+f"(c[1]), "+f"(c[2]), "+f"(c[3])
        : "r"(a0), "r"(a1), "r"(a2), "r"(a3), "r"(b0), "r"(b1));
}

template <int EPI>
__global__ void __launch_bounds__(256)
tgemm(const float* __restrict__ A, const float* __restrict__ B,
      const float* __restrict__ bias, const float* __restrict__ res,
      float* __restrict__ C, int M, int N, int K) {
    extern __shared__ float smem[];
    float* As = smem;                       // NSTAGE * A_ST
    float* Bs = smem + NSTAGE * A_ST;       // NSTAGE * B_ST

    int t = threadIdx.x;
    int lane = t & 31, warp = t >> 5;
    int wr = warp >> 2, wc = warp & 3;      // 2x4 warp grid (64x32 warp tiles)
    int m0 = blockIdx.y * BM, n0 = blockIdx.x * BN;
    int sub = lane >> 3, srow = lane & 7;   // ldmatrix addressing
    int g8 = lane >> 2, tig = lane & 3;     // mma fragment coords

    float acc[4][4][4];
    #pragma unroll
    for (int i = 0; i < 4; i++)
        #pragma unroll
        for (int j = 0; j < 4; j++)
            #pragma unroll
            for (int e = 0; e < 4; e++) acc[i][j][e] = 0.f;

    const float* Ag = A + (size_t)m0 * K;
    const float* Bg = B + n0;

    // A tile: 128m x 16k = 512 16B-chunks; ia -> m=ia>>2, kc=ia&3
    // B tile:  16k x 128n = 512 16B-chunks; ib -> k=ib>>5, nc=ib&31
    auto issue = [&](int kt) {
        int buf = kt & (NSTAGE - 1);
        int k0 = kt * BKT;
        uint32_t abase = smem_u32(As + buf * A_ST);
        uint32_t bbase = smem_u32(Bs + buf * B_ST);
        #pragma unroll
        for (int r = 0; r < 2; r++) {
            int ia = t + r * 256;
            int m = ia >> 2, kc = ia & 3;
            cp16(abase + (m * ASTR + kc * 4) * 4,
                 Ag + (size_t)m * K + k0 + kc * 4);
            int k = ia >> 5, nc = ia & 31;
            cp16(bbase + (k * BSN + nc * 4) * 4,
                 Bg + (size_t)(k0 + k) * N + nc * 4);
        }
    };

    int nk = K / BKT;
    issue(0); cp_commit();
    issue(1); cp_commit();
    issue(2); cp_commit();

    for (int kt = 0; kt < nk; kt++) {
        cp_wait<2>();
        __syncthreads();
        // keep exactly 3 groups in flight (empty groups on the tail)
        if (kt + 3 < nk) issue(kt + 3);
        cp_commit();

        int buf = kt & (NSTAGE - 1);
        const float* As_ = As + buf * A_ST;
        const float* Bs_ = Bs + buf * B_ST;

        #pragma unroll
        for (int ks = 0; ks < 2; ks++) {
            int k0 = ks * 8;
            uint32_t af[4][4];
            uint32_t bf[4][2];
            #pragma unroll
            for (int i = 0; i < 4; i++) {
                const float* base = &As_[(wr * 64 + i * 16 + (sub & 1) * 8 + srow) * ASTR
                                         + k0 + (sub >> 1) * 4];
                ldsm_x4(af[i][0], af[i][1], af[i][2], af[i][3], smem_u32(base));
            }
            #pragma unroll
            for (int j = 0; j < 4; j++) {
                const float* bp = &Bs_[(k0 + tig) * BSN + wc * 32 + j * 8 + g8];
                bf[j][0] = __float_as_uint(bp[0]);
                bf[j][1] = __float_as_uint(bp[4 * BSN]);
            }
            #pragma unroll
            for (int i = 0; i < 4; i++)
                #pragma unroll
                for (int j = 0; j < 4; j++)
                    mma_tf32(acc[i][j], af[i][0], af[i][1], af[i][2], af[i][3],
                             bf[j][0], bf[j][1]);
        }
        __syncthreads();
    }

    // epilogue: c{0,1} = row g8, cols 2*tig,2*tig+1; c{2,3} = row g8+8
    #pragma unroll
    for (int i = 0; i < 4; i++) {
        int mrow = m0 + wr * 64 + i * 16 + g8;
        #pragma unroll
        for (int j = 0; j < 4; j++) {
            int ncol = n0 + wc * 32 + j * 8 + tig * 2;
            #pragma unroll
            for (int h = 0; h < 2; h++) {
                int mm = mrow + h * 8;
                float2 v;
                v.x = acc[i][j][h * 2 + 0] + bias[ncol];
                v.y = acc[i][j][h * 2 + 1] + bias[ncol + 1];
                if (EPI == 1) {
                    const float2 r2 = *(const float2*)(res + (size_t)mm * N + ncol);
                    v.x += r2.x; v.y += r2.y;
                }
                if (EPI == 2) {
                    v.x = v.x / (1.f + __expf(-1.702f * v.x));
                    v.y = v.y / (1.f + __expf(-1.702f * v.y));
                }
                *(float2*)(C + (size_t)mm * N + ncol) = v;
            }
        }
    }
}

// ---------------- RoPE on q and k (in place on qkv buffer) -----------------
__global__ void rope_kernel(float* __restrict__ qkv,
                            const float* __restrict__ freqs) {
    int n = blockIdx.x;
    int t = threadIdx.x;
    __shared__ float fc[40], fs[40];
    if (t < 40) {
        float f = freqs[(size_t)n * 40 + t];
        fc[t] = cosf(f);
        fs[t] = sinf(f);
    }
    __syncthreads();
    for (int i = t; i < 1280; i += 256) {
        int j = i / 640;
        int rem = i - j * 640;
        int h = rem / 40;
        int d = rem - h * 40;
        float* base = qkv + (size_t)n * (3 * DIM) + j * DIM + h * HD;
        float x1 = base[d];
        float x2 = base[d + 40];
        int plo = d >> 1;
        int phi = 20 + (d >> 1);
        base[d]      = x1 * fc[plo] - x2 * fs[plo];
        base[d + 40] = x2 * fc[phi] + x1 * fs[phi];
    }
}

// ---------------- flash attention (block-diagonal via cu_seqlens) ----------
#define BQ 64
#define BK 64
#define QSTR 84
#define SSTR 68

__global__ void __launch_bounds__(256)
flash_kernel(const float* __restrict__ qkv, const int* __restrict__ cu,
             float* __restrict__ out) {
    extern __shared__ float sm[];
    float* Qs = sm;
    float* Ks = Qs + BQ * QSTR;
    float* Vs = Ks + BK * QSTR;
    float* Ss = Vs + BK * QSTR;
    __shared__ int sstart[BQ], send[BQ], sbound[2];

    int q0 = blockIdx.x * BQ;
    int h = blockIdx.y;
    int t = threadIdx.x;

    for (int i = t; i < BQ * HD; i += 256) {
        int r = i / HD, d = i - r * HD;
        Qs[r * QSTR + d] = qkv[(size_t)(q0 + r) * (3 * DIM) + h * HD + d];
    }
    if (t < BQ) {
        int row = q0 + t;
        int s = 0, e = SEQ;
        #pragma unroll
        for (int i = 0; i < 4; i++)
            if (row >= cu[i] && row < cu[i + 1]) { s = cu[i]; e = cu[i + 1]; }
        sstart[t] = s; send[t] = e;
    }
    __syncthreads();
    if (t == 0) {
        int mn = sstart[0], mx = send[0];
        for (int i = 1; i < BQ; i++) {
            mn = min(mn, sstart[i]);
            mx = max(mx, send[i]);
        }
        sbound[0] = mn; sbound[1] = mx;
    }
    __syncthreads();
    int kmin = sbound[0], kmax = sbound[1];

    int qi = t >> 2;
    int dg = t & 3;
    int mystart = sstart[qi], myend = send[qi];

    float acc[20];
    #pragma unroll
    for (int j = 0; j < 20; j++) acc[j] = 0.f;
    float m = -1e30f, l = 0.f;
    const float scale = 0.1118033988749895f;

    for (int kb = kmin; kb < kmax; kb += BK) {
        for (int i = t; i < BK * HD; i += 256) {
            int r = i / HD, d = i - r * HD;
            size_t base = (size_t)(kb + r) * (3 * DIM) + h * HD + d;
            Ks[r * QSTR + d] = qkv[base + DIM];
            Vs[r * QSTR + d] = qkv[base + 2 * DIM];
        }
        __syncthreads();

        float svals[16];
        float tmax = -1e30f;
        const float4* q4 = (const float4*)(Qs + qi * QSTR);
        #pragma unroll 4
        for (int kk = 0; kk < 16; kk++) {
            int k = kk * 4 + dg;
            const float4* k4 = (const float4*)(Ks + k * QSTR);
            float s = 0.f;
            #pragma unroll
            for (int d4 = 0; d4 < 20; d4++) {
                float4 qa = q4[d4];
                float4 ka = k4[d4];
                s += qa.x * ka.x + qa.y * ka.y + qa.z * ka.z + qa.w * ka.w;
            }
            int kg = kb + k;
            s = (kg >= mystart && kg < myend) ? s * scale : -1e30f;
            svals[kk] = s;
            tmax = fmaxf(tmax, s);
        }
        tmax = fmaxf(tmax, __shfl_xor_sync(~0u, tmax, 1));
        tmax = fmaxf(tmax, __shfl_xor_sync(~0u, tmax, 2));
        float newm = fmaxf(fmaxf(m, tmax), -1e28f);

        float psum = 0.f;
        #pragma unroll
        for (int kk = 0; kk < 16; kk++) {
            float p = __expf(svals[kk] - newm);
            psum += p;
            Ss[qi * SSTR + kk * 4 + dg] = p;
        }
        psum += __shfl_xor_sync(~0u, psum, 1);
        psum += __shfl_xor_sync(~0u, psum, 2);
        __syncwarp();

        float corr = __expf(m - newm);
        #pragma unroll
        for (int j = 0; j < 20; j++) acc[j] *= corr;
        for (int k = 0; k < BK; k++) {
            float p = Ss[qi * SSTR + k];
            const float4* v4 = (const float4*)(Vs + k * QSTR + dg * 20);
            #pragma unroll
            for (int jj = 0; jj < 5; jj++) {
                float4 vv = v4[jj];
                acc[jj * 4 + 0] += p * vv.x;
                acc[jj * 4 + 1] += p * vv.y;
                acc[jj * 4 + 2] += p * vv.z;
                acc[jj * 4 + 3] += p * vv.w;
            }
        }
        l = l * corr + psum;
        m = newm;
        __syncthreads();
    }

    float invl = 1.f / l;
    float* orow = out + (size_t)(q0 + qi) * DIM + h * HD + dg * 20;
    #pragma unroll
    for (int j = 0; j < 20; j++) orow[j] = acc[j] * invl;
}

// ---------------- launch ---------------------------------------------------
extern "C" void kernel_launch(void* const* d_in, const int* in_sizes, int n_in,
                              void* d_out, int out_size) {
    const float* hidden = (const float*)d_in[0];
    const float* rot    = (const float*)d_in[1];
    const int*   cu     = (const int*)d_in[2];
    const float* w_qkv  = (const float*)d_in[3];
    const float* b_qkv  = (const float*)d_in[4];
    const float* w_proj = (const float*)d_in[5];
    const float* b_proj = (const float*)d_in[6];
    const float* w_fc1  = (const float*)d_in[7];
    const float* b_fc1  = (const float*)d_in[8];
    const float* w_fc2  = (const float*)d_in[9];
    const float* b_fc2  = (const float*)d_in[10];
    const float* ln1s   = (const float*)d_in[11];
    const float* ln1b   = (const float*)d_in[12];
    const float* ln2s   = (const float*)d_in[13];
    const float* ln2b   = (const float*)d_in[14];
    float* out = (float*)d_out;

    float *ln, *qkvb, *attn, *h1, *fc1;
    cudaGetSymbolAddress((void**)&ln, g_ln);
    cudaGetSymbolAddress((void**)&qkvb, g_qkv);
    cudaGetSymbolAddress((void**)&attn, g_attn);
    cudaGetSymbolAddress((void**)&h1, g_h1);
    cudaGetSymbolAddress((void**)&fc1, g_fc1);

    const int FLASH_SMEM = (3 * BQ * QSTR + BQ * SSTR) * sizeof(float);
    cudaFuncSetAttribute(flash_kernel,
                         cudaFuncAttributeMaxDynamicSharedMemorySize,
                         FLASH_SMEM);
    cudaFuncSetAttribute(tgemm<0>,
                         cudaFuncAttributeMaxDynamicSharedMemorySize, GSMEM);
    cudaFuncSetAttribute(tgemm<1>,
                         cudaFuncAttributeMaxDynamicSharedMemorySize, GSMEM);
    cudaFuncSetAttribute(tgemm<2>,
                         cudaFuncAttributeMaxDynamicSharedMemorySize, GSMEM);

    // 1. LN1
    ln_kernel<<<SEQ, 256>>>(hidden, ln1s, ln1b, ln);
    // 2. QKV GEMM (+bias)
    tgemm<0><<<dim3((3 * DIM) / BN, SEQ / BM), 256, GSMEM>>>(
        ln, w_qkv, b_qkv, nullptr, qkvb, SEQ, 3 * DIM, DIM);
    // 3. RoPE on q,k
    rope_kernel<<<SEQ, 256>>>(qkvb, rot);
    // 4. attention
    flash_kernel<<<dim3(SEQ / BQ, NHEAD), 256, FLASH_SMEM>>>(qkvb, cu, attn);
    // 5. proj GEMM + bias + residual(hidden) -> h1
    tgemm<1><<<dim3(DIM / BN, SEQ / BM), 256, GSMEM>>>(
        attn, w_proj, b_proj, hidden, h1, SEQ, DIM, DIM);
    // 6. LN2
    ln_kernel<<<SEQ, 256>>>(h1, ln2s, ln2b, ln);
    // 7. FC1 + bias + quickgelu
    tgemm<2><<<dim3(HIDDEN / BN, SEQ / BM), 256, GSMEM>>>(
        ln, w_fc1, b_fc1, nullptr, fc1, SEQ, HIDDEN, DIM);
    // 8. FC2 + bias + residual(h1) -> out
    tgemm<1><<<dim3(DIM / BN, SEQ / BM), 256, GSMEM>>>(
        fc1, w_fc2, b_fc2, h1, out, SEQ, DIM, HIDDEN);
}